// round 2
// baseline (speedup 1.0000x reference)
#include <cuda_runtime.h>
#include <cuda_fp16.h>
#include <stdint.h>

// Problem: B=16, T_dec=T_enc=D=1024, fp32 I/O.
// out = [summaries: 16M floats][scores: 16M floats]
#define NB   16
#define SEQ  1024
#define HD   1024
#define NELEM (NB * SEQ * HD)   // 16,777,216

// ---------------------------------------------------------------------------
// Scratch: static __device__ arrays (allocation-free). Referenced DIRECTLY
// from device code — kernel_launch performs kernel launches only.
// ---------------------------------------------------------------------------
__device__ __half g_Qh[NELEM];   // Q fp16, [b, t, d]
__device__ __half g_Kh[NELEM];   // K fp16, [b, s, d]
__device__ __half g_Vt[NELEM];   // V^T fp16, [b, d, s]
__device__ __half g_Ph[NELEM];   // softmax probs fp16, [b, t, s]
__device__ float  g_Ssc[NELEM];  // fallback scores buffer (if out lacks scores slot)

// ---------------------------------------------------------------------------
// fp32 -> fp16 convert. DST=0 -> g_Qh, DST=1 -> g_Kh.
// ---------------------------------------------------------------------------
template <int DST>
__global__ void cvt_f32_f16(const float* __restrict__ in, int n4)
{
    __half* out = (DST == 0) ? g_Qh : g_Kh;
    int i = blockIdx.x * blockDim.x + threadIdx.x;
    if (i < n4) {
        float4 v = ((const float4*)in)[i];
        __half2 a = __floats2half2_rn(v.x, v.y);
        __half2 b = __floats2half2_rn(v.z, v.w);
        uint2 u;
        u.x = *(const uint32_t*)&a;
        u.y = *(const uint32_t*)&b;
        ((uint2*)out)[i] = u;
    }
}

// ---------------------------------------------------------------------------
// V [b, s, d] fp32 -> g_Vt [b, d, s] fp16 (tiled transpose)
// ---------------------------------------------------------------------------
__global__ void transpose_cvt(const float* __restrict__ V)
{
    __shared__ float tile[32][33];
    const int b = blockIdx.z;
    const float* Vb = V + (size_t)b * SEQ * HD;
    __half* Vtb = g_Vt + (size_t)b * HD * SEQ;

    int x  = blockIdx.x * 32 + threadIdx.x;   // d
    int y0 = blockIdx.y * 32;                 // s base
#pragma unroll
    for (int j = 0; j < 32; j += 8)
        tile[threadIdx.y + j][threadIdx.x] = Vb[(size_t)(y0 + threadIdx.y + j) * HD + x];
    __syncthreads();

    int x2 = blockIdx.y * 32 + threadIdx.x;   // s
    int y2 = blockIdx.x * 32;                 // d base
#pragma unroll
    for (int j = 0; j < 32; j += 8)
        Vtb[(size_t)(y2 + threadIdx.y + j) * SEQ + x2] =
            __float2half_rn(tile[threadIdx.x][threadIdx.y + j]);
}

// ---------------------------------------------------------------------------
// GEMM: C[m,n] = scale * sum_k A[m,k] * B'[n,k]   (A,B' row-major fp16)
// PASS=0: A=g_Qh, B'=g_Kh (logits). PASS=1: A=g_Ph, B'=g_Vt (summaries).
// CTA 128x128, K-step 32, 8 warps (2m x 4n), warp tile 64x32,
// mma.sync.m16n8k16 fp16->fp32, cp.async double-buffered.
// ---------------------------------------------------------------------------
#define BM 128
#define BN 128
#define BK 32
#define SKH 48
#define TILE_H (BM * SKH)
#define TILE_B (TILE_H * 2)

__device__ __forceinline__ void cp16(uint32_t s, const void* g)
{
    asm volatile("cp.async.cg.shared.global [%0], [%1], 16;\n" :: "r"(s), "l"(g));
}

__device__ __forceinline__ void mma_16816(float c[4], const uint32_t a[4], const uint32_t b[2])
{
    asm volatile(
        "mma.sync.aligned.m16n8k16.row.col.f32.f16.f16.f32 "
        "{%0,%1,%2,%3}, {%4,%5,%6,%7}, {%8,%9}, {%0,%1,%2,%3};\n"
        : "+f"(c[0]), "+f"(c[1]), "+f"(c[2]), "+f"(c[3])
        : "r"(a[0]), "r"(a[1]), "r"(a[2]), "r"(a[3]),
          "r"(b[0]), "r"(b[1]));
}

template <int PASS>
__global__ void __launch_bounds__(256, 2)
gemm_hf(float* __restrict__ out, int has_scores, float scale)
{
    __shared__ __half As[2][TILE_H];
    __shared__ __half Bs[2][TILE_H];

    const __half* A  = (PASS == 0) ? g_Qh : g_Ph;
    const __half* Bm = (PASS == 0) ? g_Kh : g_Vt;
    float* C;
    if (PASS == 0)
        C = has_scores ? (out + (size_t)NELEM) : g_Ssc;   // logits -> scores slot
    else
        C = out;                                          // summaries

    const int b = blockIdx.z;
    const __half* Ab = A  + (size_t)b * SEQ * HD + (size_t)blockIdx.y * BM * 1024;
    const __half* Bb = Bm + (size_t)b * SEQ * HD + (size_t)blockIdx.x * BN * 1024;
    float* Cb = C + (size_t)b * SEQ * 1024;

    const int tid  = threadIdx.x;
    const int lane = tid & 31, wid = tid >> 5;
    const int wm = wid & 1, wn = wid >> 1;
    const int g  = lane >> 2, tc = lane & 3;

    const int r0 = tid >> 2;
    const int s0 = tid & 3;

    uint32_t as_u = (uint32_t)__cvta_generic_to_shared(&As[0][0]);
    uint32_t bs_u = (uint32_t)__cvta_generic_to_shared(&Bs[0][0]);

    float acc[4][4][4];
#pragma unroll
    for (int mi = 0; mi < 4; mi++)
#pragma unroll
        for (int ni = 0; ni < 4; ni++)
#pragma unroll
            for (int i = 0; i < 4; i++) acc[mi][ni][i] = 0.0f;

    const int NT = 1024 / BK;

    {   // prologue: tile 0 -> buffer 0
        const __half* ga = Ab + (size_t)r0 * 1024 + s0 * 8;
        const __half* gb = Bb + (size_t)r0 * 1024 + s0 * 8;
        uint32_t sa = as_u + (r0 * SKH + s0 * 8) * 2;
        uint32_t sb = bs_u + (r0 * SKH + s0 * 8) * 2;
        cp16(sa, ga);  cp16(sa + 64 * SKH * 2, ga + 64 * 1024);
        cp16(sb, gb);  cp16(sb + 64 * SKH * 2, gb + 64 * 1024);
        asm volatile("cp.async.commit_group;\n");
    }

    for (int kt = 0; kt < NT; ++kt) {
        const int buf = kt & 1;
        if (kt + 1 < NT) {
            const int k0 = (kt + 1) * BK;
            const __half* ga = Ab + (size_t)r0 * 1024 + k0 + s0 * 8;
            const __half* gb = Bb + (size_t)r0 * 1024 + k0 + s0 * 8;
            uint32_t sa = as_u + (buf ^ 1) * TILE_B + (r0 * SKH + s0 * 8) * 2;
            uint32_t sb = bs_u + (buf ^ 1) * TILE_B + (r0 * SKH + s0 * 8) * 2;
            cp16(sa, ga);  cp16(sa + 64 * SKH * 2, ga + 64 * 1024);
            cp16(sb, gb);  cp16(sb + 64 * SKH * 2, gb + 64 * 1024);
            asm volatile("cp.async.commit_group;\n");
            asm volatile("cp.async.wait_group 1;\n");
        } else {
            asm volatile("cp.async.wait_group 0;\n");
        }
        __syncthreads();

        const __half* as = &As[buf][0];
        const __half* bs = &Bs[buf][0];
#pragma unroll
        for (int ks = 0; ks < BK; ks += 16) {
            uint32_t af[4][4], bf[4][2];
#pragma unroll
            for (int mi = 0; mi < 4; mi++) {
                const __half* ap = as + (wm * 64 + mi * 16 + g) * SKH + ks + tc * 2;
                af[mi][0] = *(const uint32_t*)(ap);
                af[mi][1] = *(const uint32_t*)(ap + 8 * SKH);
                af[mi][2] = *(const uint32_t*)(ap + 8);
                af[mi][3] = *(const uint32_t*)(ap + 8 * SKH + 8);
            }
#pragma unroll
            for (int ni = 0; ni < 4; ni++) {
                const __half* bp = bs + (wn * 32 + ni * 8 + g) * SKH + ks + tc * 2;
                bf[ni][0] = *(const uint32_t*)(bp);
                bf[ni][1] = *(const uint32_t*)(bp + 8);
            }
#pragma unroll
            for (int mi = 0; mi < 4; mi++)
#pragma unroll
                for (int ni = 0; ni < 4; ni++)
                    mma_16816(acc[mi][ni], af[mi], bf[ni]);
        }
        __syncthreads();
    }

#pragma unroll
    for (int mi = 0; mi < 4; mi++) {
        const int gr = blockIdx.y * BM + wm * 64 + mi * 16 + g;
#pragma unroll
        for (int ni = 0; ni < 4; ni++) {
            const int gc = blockIdx.x * BN + wn * 32 + ni * 8 + tc * 2;
            float2 v0 = make_float2(acc[mi][ni][0] * scale, acc[mi][ni][1] * scale);
            float2 v1 = make_float2(acc[mi][ni][2] * scale, acc[mi][ni][3] * scale);
            *(float2*)&Cb[(size_t)gr * 1024 + gc]       = v0;
            *(float2*)&Cb[(size_t)(gr + 8) * 1024 + gc] = v1;
        }
    }
}

// ---------------------------------------------------------------------------
// Row softmax in place on fp32 logits + fp16 probs to g_Ph.
// One 128-thread CTA per row.
// ---------------------------------------------------------------------------
__global__ void softmax_rw(float* __restrict__ out, int has_scores)
{
    float* S = has_scores ? (out + (size_t)NELEM) : g_Ssc;
    const int row = blockIdx.x;
    float* sp = S + (size_t)row * SEQ;
    const int t = threadIdx.x;

    float4 v0 = ((float4*)sp)[t];
    float4 v1 = ((float4*)sp)[t + 128];

    float m = fmaxf(fmaxf(fmaxf(v0.x, v0.y), fmaxf(v0.z, v0.w)),
                    fmaxf(fmaxf(v1.x, v1.y), fmaxf(v1.z, v1.w)));
#pragma unroll
    for (int o = 16; o; o >>= 1) m = fmaxf(m, __shfl_xor_sync(0xffffffffu, m, o));

    __shared__ float rmax[4], rsum[4];
    const int w = t >> 5, l = t & 31;
    if (l == 0) rmax[w] = m;
    __syncthreads();
    m = fmaxf(fmaxf(rmax[0], rmax[1]), fmaxf(rmax[2], rmax[3]));

    float e[8];
    e[0] = __expf(v0.x - m); e[1] = __expf(v0.y - m);
    e[2] = __expf(v0.z - m); e[3] = __expf(v0.w - m);
    e[4] = __expf(v1.x - m); e[5] = __expf(v1.y - m);
    e[6] = __expf(v1.z - m); e[7] = __expf(v1.w - m);

    float s = e[0] + e[1] + e[2] + e[3] + e[4] + e[5] + e[6] + e[7];
#pragma unroll
    for (int o = 16; o; o >>= 1) s += __shfl_xor_sync(0xffffffffu, s, o);
    if (l == 0) rsum[w] = s;
    __syncthreads();
    s = rsum[0] + rsum[1] + rsum[2] + rsum[3];

    const float inv = 1.0f / s;
#pragma unroll
    for (int i = 0; i < 8; i++) e[i] *= inv;

    ((float4*)sp)[t]       = make_float4(e[0], e[1], e[2], e[3]);
    ((float4*)sp)[t + 128] = make_float4(e[4], e[5], e[6], e[7]);

    __half* pp = g_Ph + (size_t)row * SEQ;
    __half2 h0 = __floats2half2_rn(e[0], e[1]);
    __half2 h1 = __floats2half2_rn(e[2], e[3]);
    __half2 h2 = __floats2half2_rn(e[4], e[5]);
    __half2 h3 = __floats2half2_rn(e[6], e[7]);
    uint2 u0 = make_uint2(*(uint32_t*)&h0, *(uint32_t*)&h1);
    uint2 u1 = make_uint2(*(uint32_t*)&h2, *(uint32_t*)&h3);
    ((uint2*)pp)[t]       = u0;
    ((uint2*)pp)[t + 128] = u1;
}

// ---------------------------------------------------------------------------
// Launch sequence: converts -> GEMM1 -> softmax -> GEMM2.
// Pure kernel launches: no CUDA API calls besides <<<>>>.
// ---------------------------------------------------------------------------
extern "C" void kernel_launch(void* const* d_in, const int* in_sizes, int n_in,
                              void* d_out, int out_size)
{
    const float* Q = (const float*)d_in[0];
    const float* K = (const float*)d_in[1];
    const float* V = (const float*)d_in[2];
    float* out = (float*)d_out;
    const int has_scores = (out_size >= 2 * NELEM) ? 1 : 0;

    const int n4 = NELEM / 4;
    cvt_f32_f16<0><<<n4 / 256, 256>>>(Q, n4);
    cvt_f32_f16<1><<<n4 / 256, 256>>>(K, n4);
    transpose_cvt<<<dim3(SEQ / 32, SEQ / 32, NB), dim3(32, 8)>>>(V);

    // logits = Q K^T / 32  -> scores slot (or fallback)
    gemm_hf<0><<<dim3(8, 8, NB), 256>>>(out, has_scores, 1.0f / 32.0f);
    // softmax rows in place, fp16 probs to g_Ph
    softmax_rw<<<NB * SEQ, 128>>>(out, has_scores);
    // summaries = P V
    gemm_hf<1><<<dim3(8, 8, NB), 256>>>(out, has_scores, 1.0f);
}

// round 4
// speedup vs baseline: 1.3105x; 1.3105x over previous
#include <cuda_runtime.h>
#include <cuda_fp16.h>
#include <stdint.h>

// Problem: B=16, T_dec=T_enc=D=1024, fp32 I/O.
// out = [summaries: 16M floats][scores: 16M floats]
// NOTE: harness compiles for baseline sm_100 (no 'a' features). tcgen05 is
// unavailable; best tensor path is mma.sync HMMA + cp.async + ldmatrix.
#define NB   16
#define SEQ  1024
#define HD   1024
#define NELEM (NB * SEQ * HD)

// ---------------------------------------------------------------------------
// Scratch (static __device__, allocation-free)
// ---------------------------------------------------------------------------
__device__ __half g_Qh[NELEM];   // Q * (1/32) fp16, [b, t, d]
__device__ __half g_Kh[NELEM];   // K fp16, [b, s, d]
__device__ __half g_Vt[NELEM];   // V^T fp16, [b, d, s]
__device__ __half g_Ph[NELEM];   // softmax probs fp16, [b, t, s]
__device__ float  g_Ssc[NELEM];  // fallback scores buffer

// ---------------------------------------------------------------------------
// fp32 -> fp16 convert; DST=0: Q*(1/32) -> g_Qh, DST=1: K -> g_Kh
// (full softmax scale 1/sqrt(1024)=1/32 folded exactly into Q)
// ---------------------------------------------------------------------------
template <int DST>
__global__ void cvt_f32_f16(const float* __restrict__ in, int n4)
{
    __half* out = (DST == 0) ? g_Qh : g_Kh;
    const float sc = (DST == 0) ? 0.03125f : 1.0f;
    int i = blockIdx.x * blockDim.x + threadIdx.x;
    if (i < n4) {
        float4 v = ((const float4*)in)[i];
        __half2 a = __floats2half2_rn(v.x * sc, v.y * sc);
        __half2 b = __floats2half2_rn(v.z * sc, v.w * sc);
        uint2 u;
        u.x = *(const uint32_t*)&a;
        u.y = *(const uint32_t*)&b;
        ((uint2*)out)[i] = u;
    }
}

// ---------------------------------------------------------------------------
// V [b, s, d] fp32 -> g_Vt [b, d, s] fp16
// ---------------------------------------------------------------------------
__global__ void transpose_cvt(const float* __restrict__ V)
{
    __shared__ float tile[32][33];
    const int b = blockIdx.z;
    const float* Vb = V + (size_t)b * SEQ * HD;
    __half* Vtb = g_Vt + (size_t)b * HD * SEQ;

    int x  = blockIdx.x * 32 + threadIdx.x;
    int y0 = blockIdx.y * 32;
#pragma unroll
    for (int j = 0; j < 32; j += 8)
        tile[threadIdx.y + j][threadIdx.x] = Vb[(size_t)(y0 + threadIdx.y + j) * HD + x];
    __syncthreads();

    int x2 = blockIdx.y * 32 + threadIdx.x;
    int y2 = blockIdx.x * 32;
#pragma unroll
    for (int j = 0; j < 32; j += 8)
        Vtb[(size_t)(y2 + threadIdx.y + j) * SEQ + x2] =
            __float2half_rn(tile[threadIdx.x][threadIdx.y + j]);
}

// ---------------------------------------------------------------------------
// HMMA GEMM: C[m,n] = sum_k A[m,k] * B'[n,k]  (A,B' row-major fp16, C fp32)
// CTA 128x128, BK=64, 3-stage cp.async ring, ldmatrix.x4 fragment loads,
// 8 warps (2m x 4n), warp tile 64x32, mma.m16n8k16.
// PASS=0: A=g_Qh, B'=g_Kh -> logits. PASS=1: A=g_Ph, B'=g_Vt -> summaries.
// ---------------------------------------------------------------------------
#define BM 128
#define BN 128
#define BK 64
#define STAGES  3
#define STAGE_A (BM * BK * 2)            // 16384 bytes (A half of a stage)
#define STAGE_BYTES (2 * STAGE_A)        // 32768 bytes (A + B)
#define GEMM_SMEM (STAGES * STAGE_BYTES) // 98304 bytes

__device__ __forceinline__ uint32_t smem_u32(const void* p) {
    uint32_t a;
    asm("{ .reg .u64 t; cvta.to.shared.u64 t, %1; cvt.u32.u64 %0, t; }" : "=r"(a) : "l"(p));
    return a;
}
__device__ __forceinline__ void cp16(uint32_t s, const void* g)
{
    asm volatile("cp.async.cg.shared.global [%0], [%1], 16;\n" :: "r"(s), "l"(g));
}
__device__ __forceinline__ void ldsm_x4(uint32_t r[4], uint32_t addr)
{
    asm volatile("ldmatrix.sync.aligned.m8n8.x4.shared.b16 {%0,%1,%2,%3}, [%4];"
                 : "=r"(r[0]), "=r"(r[1]), "=r"(r[2]), "=r"(r[3]) : "r"(addr));
}
__device__ __forceinline__ void mma_16816(float c[4], const uint32_t a[4],
                                          uint32_t b0, uint32_t b1)
{
    asm volatile(
        "mma.sync.aligned.m16n8k16.row.col.f32.f16.f16.f32 "
        "{%0,%1,%2,%3}, {%4,%5,%6,%7}, {%8,%9}, {%0,%1,%2,%3};\n"
        : "+f"(c[0]), "+f"(c[1]), "+f"(c[2]), "+f"(c[3])
        : "r"(a[0]), "r"(a[1]), "r"(a[2]), "r"(a[3]), "r"(b0), "r"(b1));
}

// One K-chunk (BK=64 halfs = 8 x 16B segments per row) for A and B tiles.
// Swizzle: seg' = seg XOR (row & 7)  -> conflict-free ldmatrix + cp.async.
__device__ __forceinline__ void load_chunk(const __half* gA, const __half* gB,
                                           uint32_t sA, uint32_t sB, int kc, int tid)
{
#pragma unroll
    for (int i = 0; i < 4; i++) {
        int idx = i * 256 + tid;          // 1024 16B-segments for A
        int row = idx >> 3, seg = idx & 7;
        cp16(sA + row * 128 + (((seg ^ (row & 7))) << 4),
             gA + (size_t)row * 1024 + kc * 64 + seg * 8);
    }
#pragma unroll
    for (int i = 0; i < 4; i++) {
        int idx = i * 256 + tid;
        int row = idx >> 3, seg = idx & 7;
        cp16(sB + row * 128 + (((seg ^ (row & 7))) << 4),
             gB + (size_t)row * 1024 + kc * 64 + seg * 8);
    }
}

template <int PASS>
__global__ void __launch_bounds__(256, 2)
gemm_hm(float* __restrict__ out, int has_scores)
{
    extern __shared__ __align__(1024) char smem[];
    const uint32_t sbase = smem_u32(smem);

    const __half* A  = (PASS == 0) ? g_Qh : g_Ph;
    const __half* Bm = (PASS == 0) ? g_Kh : g_Vt;
    float* C = (PASS == 0) ? (has_scores ? ((float*)out + (size_t)NELEM) : g_Ssc) : out;

    const int b = blockIdx.z;
    const __half* Ab = A  + (size_t)b * SEQ * HD + (size_t)blockIdx.y * BM * 1024;
    const __half* Bb = Bm + (size_t)b * SEQ * HD + (size_t)blockIdx.x * BN * 1024;
    float* Cb = C + (size_t)b * SEQ * 1024;

    const int tid  = threadIdx.x;
    const int lane = tid & 31, wid = tid >> 5;
    const int wm = wid & 1, wn = wid >> 1;          // 2 (m) x 4 (n) warps
    const int g  = lane >> 2, tc = lane & 3;        // mma accumulator coords
    const int l15 = lane & 15, lhi = lane >> 4;     // ldmatrix coords

    float acc[4][4][4];
#pragma unroll
    for (int mi = 0; mi < 4; mi++)
#pragma unroll
        for (int ni = 0; ni < 4; ni++)
#pragma unroll
            for (int i = 0; i < 4; i++) acc[mi][ni][i] = 0.0f;

    const int NCHUNK = 1024 / BK;   // 16

    // prologue: chunks 0,1 -> stages 0,1
    load_chunk(Ab, Bb, sbase, sbase + STAGE_A, 0, tid);
    asm volatile("cp.async.commit_group;\n");
    load_chunk(Ab, Bb, sbase + STAGE_BYTES, sbase + STAGE_BYTES + STAGE_A, 1, tid);
    asm volatile("cp.async.commit_group;\n");

    for (int k = 0; k < NCHUNK; ++k) {
        if (k < NCHUNK - 1) asm volatile("cp.async.wait_group 1;\n");
        else                asm volatile("cp.async.wait_group 0;\n");
        __syncthreads();

        // prefetch chunk k+2 into stage (k+2)%3 (consumed at iter k-1; safe)
        if (k + 2 < NCHUNK) {
            uint32_t sA = sbase + ((k + 2) % 3) * STAGE_BYTES;
            load_chunk(Ab, Bb, sA, sA + STAGE_A, k + 2, tid);
            asm volatile("cp.async.commit_group;\n");
        }

        const uint32_t sA = sbase + (k % 3) * STAGE_BYTES;
        const uint32_t sB = sA + STAGE_A;

#pragma unroll
        for (int j = 0; j < 4; j++) {                   // 4 x k16 within BK=64
            uint32_t af[4][4], bf[2][4];
#pragma unroll
            for (int mi = 0; mi < 4; mi++) {
                int row = wm * 64 + mi * 16 + l15;
                int seg = (j * 2 + lhi) ^ (row & 7);
                ldsm_x4(af[mi], sA + row * 128 + (seg << 4));
            }
#pragma unroll
            for (int nj = 0; nj < 2; nj++) {
                int row = wn * 32 + nj * 16 + l15;
                int seg = (j * 2 + lhi) ^ (row & 7);
                ldsm_x4(bf[nj], sB + row * 128 + (seg << 4));
            }
#pragma unroll
            for (int mi = 0; mi < 4; mi++)
#pragma unroll
                for (int ni = 0; ni < 4; ni++) {
                    const int nj = ni >> 1, hi = ni & 1;
                    mma_16816(acc[mi][ni], af[mi], bf[nj][hi], bf[nj][2 + hi]);
                }
        }
        __syncthreads();
    }

    // epilogue: direct strided float2 stores
#pragma unroll
    for (int mi = 0; mi < 4; mi++) {
        const int gr = blockIdx.y * BM + wm * 64 + mi * 16 + g;
#pragma unroll
        for (int ni = 0; ni < 4; ni++) {
            const int gc = blockIdx.x * BN + wn * 32 + ni * 8 + tc * 2;
            float2 v0 = make_float2(acc[mi][ni][0], acc[mi][ni][1]);
            float2 v1 = make_float2(acc[mi][ni][2], acc[mi][ni][3]);
            *(float2*)&Cb[(size_t)gr * 1024 + gc]       = v0;
            *(float2*)&Cb[(size_t)(gr + 8) * 1024 + gc] = v1;
        }
    }
}

// ---------------------------------------------------------------------------
// Row softmax in place + fp16 probs to g_Ph. One 128-thread CTA per row.
// ---------------------------------------------------------------------------
__global__ void softmax_rw(float* __restrict__ out, int has_scores)
{
    float* S = has_scores ? ((float*)out + (size_t)NELEM) : g_Ssc;
    const int row = blockIdx.x;
    float* sp = S + (size_t)row * SEQ;
    const int t = threadIdx.x;

    float4 v0 = ((float4*)sp)[t];
    float4 v1 = ((float4*)sp)[t + 128];

    float m = fmaxf(fmaxf(fmaxf(v0.x, v0.y), fmaxf(v0.z, v0.w)),
                    fmaxf(fmaxf(v1.x, v1.y), fmaxf(v1.z, v1.w)));
#pragma unroll
    for (int o = 16; o; o >>= 1) m = fmaxf(m, __shfl_xor_sync(0xffffffffu, m, o));

    __shared__ float rmax[4], rsum[4];
    const int w = t >> 5, l = t & 31;
    if (l == 0) rmax[w] = m;
    __syncthreads();
    m = fmaxf(fmaxf(rmax[0], rmax[1]), fmaxf(rmax[2], rmax[3]));

    float e[8];
    e[0] = __expf(v0.x - m); e[1] = __expf(v0.y - m);
    e[2] = __expf(v0.z - m); e[3] = __expf(v0.w - m);
    e[4] = __expf(v1.x - m); e[5] = __expf(v1.y - m);
    e[6] = __expf(v1.z - m); e[7] = __expf(v1.w - m);

    float s = e[0] + e[1] + e[2] + e[3] + e[4] + e[5] + e[6] + e[7];
#pragma unroll
    for (int o = 16; o; o >>= 1) s += __shfl_xor_sync(0xffffffffu, s, o);
    if (l == 0) rsum[w] = s;
    __syncthreads();
    s = rsum[0] + rsum[1] + rsum[2] + rsum[3];

    const float inv = 1.0f / s;
#pragma unroll
    for (int i = 0; i < 8; i++) e[i] *= inv;

    ((float4*)sp)[t]       = make_float4(e[0], e[1], e[2], e[3]);
    ((float4*)sp)[t + 128] = make_float4(e[4], e[5], e[6], e[7]);

    __half* pp = g_Ph + (size_t)row * SEQ;
    __half2 h0 = __floats2half2_rn(e[0], e[1]);
    __half2 h1 = __floats2half2_rn(e[2], e[3]);
    __half2 h2 = __floats2half2_rn(e[4], e[5]);
    __half2 h3 = __floats2half2_rn(e[6], e[7]);
    uint2 u0 = make_uint2(*(uint32_t*)&h0, *(uint32_t*)&h1);
    uint2 u1 = make_uint2(*(uint32_t*)&h2, *(uint32_t*)&h3);
    ((uint2*)pp)[t]       = u0;
    ((uint2*)pp)[t + 128] = u1;
}

// ---------------------------------------------------------------------------
// Launch: converts -> GEMM1 -> softmax -> GEMM2
// ---------------------------------------------------------------------------
extern "C" void kernel_launch(void* const* d_in, const int* in_sizes, int n_in,
                              void* d_out, int out_size)
{
    const float* Q = (const float*)d_in[0];
    const float* K = (const float*)d_in[1];
    const float* V = (const float*)d_in[2];
    float* out = (float*)d_out;
    const int has_scores = (out_size >= 2 * NELEM) ? 1 : 0;

    cudaFuncSetAttribute(gemm_hm<0>, cudaFuncAttributeMaxDynamicSharedMemorySize, GEMM_SMEM);
    cudaFuncSetAttribute(gemm_hm<1>, cudaFuncAttributeMaxDynamicSharedMemorySize, GEMM_SMEM);

    const int n4 = NELEM / 4;
    cvt_f32_f16<0><<<n4 / 256, 256>>>(Q, n4);
    cvt_f32_f16<1><<<n4 / 256, 256>>>(K, n4);
    transpose_cvt<<<dim3(SEQ / 32, SEQ / 32, NB), dim3(32, 8)>>>(V);

    gemm_hm<0><<<dim3(8, 8, NB), 256, GEMM_SMEM>>>(out, has_scores);   // logits
    softmax_rw<<<NB * SEQ, 128>>>(out, has_scores);
    gemm_hm<1><<<dim3(8, 8, NB), 256, GEMM_SMEM>>>(out, has_scores);   // summaries
}